// round 8
// baseline (speedup 1.0000x reference)
#include <cuda_runtime.h>

#define EPSF     1.1920928955078125e-07f
#define LOG2E    1.4426950408889634f
#define NSAMP    2000
#define NPAD     2048
#define Y0F      0.9999f
#define NROWS    65536
#define MAGICF   12582912.0f     // 1.5 * 2^23
#define FULLMASK 0xffffffffu

#define NCH      16      // chunks per row
#define CPT      8       // chunks per thread (2 threads/row)
#define CPTS     128     // points per chunk
#define CF4      64      // float4 per chunk
#define CF4P     65      // padded chunk stride (float4 units)
// +1 float4 skew between chunk 7 and 8 so pair-halves hit disjoint banks
#define TABSZ    (NCH * CF4P + 1)

__device__ float4 g_tabC[TABSZ];
__device__ float  g_grid[NPAD];

typedef unsigned long long u64;
typedef unsigned int u32;

__device__ __forceinline__ float ex2(float x) {
    float r;
    asm("ex2.approx.ftz.f32 %0, %1;" : "=f"(r) : "f"(x));
    return r;
}
__device__ __forceinline__ u64 pk(float a, float b) {
    u64 r;
    asm("mov.b64 %0, {%1, %2};" : "=l"(r) : "f"(a), "f"(b));
    return r;
}
__device__ __forceinline__ void upk(float& a, float& b, u64 r) {
    asm("mov.b64 {%0, %1}, %2;" : "=f"(a), "=f"(b) : "l"(r));
}
#define ADD2(d,a,b) asm("add.rn.f32x2 %0, %1, %2;"     : "=l"(d) : "l"(a), "l"(b))
#define SUB2(d,a,b) asm("sub.rn.f32x2 %0, %1, %2;"     : "=l"(d) : "l"(a), "l"(b))
#define MUL2(d,a,b) asm("mul.rn.f32x2 %0, %1, %2;"     : "=l"(d) : "l"(a), "l"(b))
#define FMA2(d,a,b,c) asm("fma.rn.f32x2 %0, %1, %2, %3;" : "=l"(d) : "l"(a), "l"(b), "l"(c))

#define TPB      128
#define NBLK     (NROWS * 2 / TPB)   // 1024

__device__ __forceinline__ int chunk_base(int c) { return c * CF4P + (c >> 3); }

__global__ void init_tables_kernel() {
    int i = blockIdx.x * blockDim.x + threadIdx.x;  // 0..2047
    if (i >= NPAD) return;
    const float step = 2.0f * Y0F / 1999.0f;
    float ax, l2, g;
    if (i < NSAMP) {
        float x = (i == NSAMP - 1) ? Y0F
                                   : __fadd_rn(__fmul_rn((float)i, step), -Y0F);
        ax = 0.5f * logf((1.0f + x) / (1.0f - x) + EPSF);
        l2 = -log2f(1.0f - x * x);
        g  = x;
    } else {
        ax = 0.0f; l2 = -1e30f; g = Y0F;   // padding inert
    }
    g_grid[i] = g;
    int c = i >> 7, q = (i & 127) >> 1, h = i & 1;
    float* f = (float*)&g_tabC[chunk_base(c) + q];
    f[h]     = ax;
    f[2 + h] = l2;
}

// 2 threads per row: thread half h owns chunks [8h, 8h+8).
__global__ __launch_bounds__(TPB) void sample_kernel(
    const float* __restrict__ mean,
    const float* __restrict__ stdv,
    const float* __restrict__ uni,
    float* __restrict__ out)
{
    __shared__ float4 tab[TABSZ];   // 16656 B

    const int tid  = threadIdx.x;
    for (int i = tid; i < TABSZ; i += TPB) tab[i] = g_tabC[i];
    __syncthreads();

    const int gt   = blockIdx.x * TPB + tid;
    const int row  = gt >> 1;
    const int half = gt & 1;
    const int lane = tid & 31;

    const float mu = __ldg(mean + row);
    const float sg = __ldg(stdv + row) + EPSF;
    const float u  = __ldg(uni + row);
    const float k2 = (-0.5f * LOG2E) / (sg * sg);

    const u64 nmu   = pk(-mu, -mu);
    const u64 k2p   = pk(k2, k2);
    const u64 magicP = pk(MAGICF, MAGICF);
    const u64 c5p = pk(1.3333558e-3f, 1.3333558e-3f);
    const u64 c4p = pk(9.6181291e-3f, 9.6181291e-3f);
    const u64 c3p = pk(5.5504109e-2f, 5.5504109e-2f);
    const u64 c2p = pk(2.4022651e-1f, 2.4022651e-1f);
    const u64 c1p = pk(6.9314718e-1f, 6.9314718e-1f);
    const u64 c0p = pk(1.0f, 1.0f);

    // ---- Phase 1: my 8 chunk sums (registers); hybrid MUFU/poly exp ----
    float cs[CPT];
    float ps = 0.0f;
    #pragma unroll
    for (int c = 0; c < CPT; ++c) {
        const float4* cp = tab + chunk_base(half * CPT + c);
        float s0 = 0.0f, s1 = 0.0f;
        u64 sp = pk(0.0f, 0.0f);
        #pragma unroll 16
        for (int j = 0; j < CF4; ++j) {
            float4 v = cp[j];  // broadcast LDS.128, pair-halves on disjoint banks
            u64 axp = pk(v.x, v.y);
            u64 l2p = pk(v.z, v.w);
            u64 t, tt, arg;
            ADD2(t, axp, nmu);
            MUL2(tt, t, t);
            FMA2(arg, tt, k2p, l2p);
            if ((j & 15) < 3) {
                // packed poly exp2 on fma pipe (beta = 3/16); clamp on alu pipe
                float alo, ahi;
                upk(alo, ahi, arg);
                alo = fmaxf(alo, -120.0f);
                ahi = fmaxf(ahi, -120.0f);
                arg = pk(alo, ahi);
                u64 m, iv, f, p;
                ADD2(m, arg, magicP);
                SUB2(iv, m, magicP);
                SUB2(f, arg, iv);
                FMA2(p, c5p, f, c4p);
                FMA2(p, p,  f, c3p);
                FMA2(p, p,  f, c2p);
                FMA2(p, p,  f, c1p);
                FMA2(p, p,  f, c0p);
                u32 mlo = (u32)m, mhi = (u32)(m >> 32);
                u32 plo = (u32)p, phi = (u32)(p >> 32);
                float rlo = __uint_as_float(plo + (mlo << 23));
                float rhi = __uint_as_float(phi + (mhi << 23));
                u64 r = pk(rlo, rhi);
                ADD2(sp, sp, r);
            } else {
                float lo, hi;
                upk(lo, hi, arg);
                s0 += ex2(lo);
                s1 += ex2(hi);
            }
        }
        float splo, sphi;
        upk(splo, sphi, sp);
        float v = (s0 + s1) + (splo + sphi);
        cs[c] = v;
        ps += v;        // same order as the cum walk below -> bit-consistent
    }

    // ---- Pair handoff: excl (exact boundary) and shared S ----
    float pso = __shfl_xor_sync(FULLMASK, ps, 1);     // partner's ps
    float excl = half ? pso : 0.0f;
    float cum = excl;
    #pragma unroll
    for (int c = 0; c < CPT; ++c) cum += cs[c];
    // S = half1's final cum == exact sequential full sum; broadcast to both
    float S = __shfl_sync(FULLMASK, cum, lane | 1);

    const float invnorm = rsqrtf(6.283185307179586f * sg * sg);
    const float denom   = __fmaf_rn(invnorm, S, EPSF);
    const float Traw    = u * denom / invnorm;

    // ---- Phase 2a: crossing chunk within my half ----
    int kc = -1;
    float base = 0.0f;
    float c2w = excl;
    #pragma unroll
    for (int c = 0; c < CPT; ++c) {
        float ni = c2w + cs[c];
        if (kc < 0 && ni > Traw) { kc = half * CPT + c; base = c2w; }
        c2w = ni;
    }
    if (excl > Traw) kc = -1;   // partner already crossed

    unsigned bal = __ballot_sync(FULLMASK, kc >= 0);
    bool pair_none = (((bal >> (lane & ~1)) & 3u) == 0u);
    bool am_writer = (kc >= 0) || (pair_none && half == 1);

    if (am_writer) {
        int idx;
        if (kc < 0) {
            float Snorm = invnorm * S;
            float cl = Snorm / (Snorm + EPSF);   // reference's cdf[last]
            idx = (u < cl) ? (NSAMP - 1) : 0;
        } else {
            // ---- Phase 2b: rewalk crossing chunk (exact ex2) ----
            const float T2 = Traw - base;
            const float4* cp = tab + chunk_base(kc);
            float c = 0.0f;
            idx = -1;
            #pragma unroll 8
            for (int j = 0; j < CF4; ++j) {
                float4 v = cp[j];
                float t0 = v.x - mu;
                float p0 = ex2(__fmaf_rn(t0 * t0, k2, v.z));
                c += p0;
                if (idx < 0 && c > T2) idx = kc * CPTS + 2 * j;
                float t1 = v.y - mu;
                float p1 = ex2(__fmaf_rn(t1 * t1, k2, v.w));
                c += p1;
                if (idx < 0 && c > T2) idx = kc * CPTS + 2 * j + 1;
            }
            if (idx < 0) idx = kc * CPTS + CPTS - 1;
            if (idx > NSAMP - 1) idx = NSAMP - 1;
        }

        // ---- Recompute prob at final index (exact ex2) ----
        int cc = idx >> 7, q = (idx & 127) >> 1, h = idx & 1;
        float4 v = tab[chunk_base(cc) + q];
        float ax = h ? v.y : v.x;
        float l2 = h ? v.w : v.z;
        float t = ax - mu;
        float p = ex2(__fmaf_rn(t * t, k2, l2));
        float prob = invnorm * p / denom;

        out[row]         = __ldg(g_grid + idx);
        out[NROWS + row] = prob;
    }
}

extern "C" void kernel_launch(void* const* d_in, const int* in_sizes, int n_in,
                              void* d_out, int out_size) {
    const float* mean = (const float*)d_in[0];
    const float* stdv = (const float*)d_in[1];
    const float* uni  = (const float*)d_in[2];
    float* out = (float*)d_out;

    init_tables_kernel<<<2, 1024>>>();
    sample_kernel<<<NBLK, TPB>>>(mean, stdv, uni, out);
}

// round 9
// speedup vs baseline: 1.0529x; 1.0529x over previous
#include <cuda_runtime.h>

#define EPSF     1.1920928955078125e-07f
#define LOG2E    1.4426950408889634f
#define NSAMP    2000
#define NPAD     2048
#define Y0F      0.9999f
#define NROWS    65536
#define MAGICF   12582912.0f     // 1.5 * 2^23
#define FULLMASK 0xffffffffu

#define NCH      16      // chunks per row
#define CPT      8       // chunks per thread (2 threads/row)
#define CPTS     128     // points per chunk
#define CF4      64      // 16B-pairs per chunk
#define CF4P     65      // padded chunk stride (16B units)
#define TABSZ    (NCH * CF4P + 1)

// Table entry: .x = (ax_{2i}, ax_{2i+1}) packed, .y = (l2_{2i}, l2_{2i+1}) packed.
__device__ ulonglong2 g_tabU[TABSZ];
__device__ float      g_grid[NPAD];

typedef unsigned long long u64;
typedef unsigned int u32;

__device__ __forceinline__ float ex2(float x) {
    float r;
    asm("ex2.approx.ftz.f32 %0, %1;" : "=f"(r) : "f"(x));
    return r;
}
__device__ __forceinline__ u64 pk(float a, float b) {
    u64 r;
    asm("mov.b64 %0, {%1, %2};" : "=l"(r) : "f"(a), "f"(b));
    return r;
}
__device__ __forceinline__ void upk(float& a, float& b, u64 r) {
    asm("mov.b64 {%0, %1}, %2;" : "=f"(a), "=f"(b) : "l"(r));
}
#define ADD2(d,a,b) asm("add.rn.f32x2 %0, %1, %2;"     : "=l"(d) : "l"(a), "l"(b))
#define SUB2(d,a,b) asm("sub.rn.f32x2 %0, %1, %2;"     : "=l"(d) : "l"(a), "l"(b))
#define MUL2(d,a,b) asm("mul.rn.f32x2 %0, %1, %2;"     : "=l"(d) : "l"(a), "l"(b))
#define FMA2(d,a,b,c) asm("fma.rn.f32x2 %0, %1, %2, %3;" : "=l"(d) : "l"(a), "l"(b), "l"(c))

#define TPB      128
#define NBLK     (NROWS * 2 / TPB)   // 1024

__device__ __forceinline__ int chunk_base(int c) { return c * CF4P + (c >> 3); }

__global__ void init_tables_kernel() {
    int i = blockIdx.x * blockDim.x + threadIdx.x;  // 0..2047
    if (i >= NPAD) return;
    const float step = 2.0f * Y0F / 1999.0f;
    float ax, l2, g;
    if (i < NSAMP) {
        float x = (i == NSAMP - 1) ? Y0F
                                   : __fadd_rn(__fmul_rn((float)i, step), -Y0F);
        ax = 0.5f * logf((1.0f + x) / (1.0f - x) + EPSF);
        l2 = -log2f(1.0f - x * x);
        g  = x;
    } else {
        ax = 0.0f; l2 = -1e30f; g = Y0F;   // padding inert
    }
    g_grid[i] = g;
    int c = i >> 7, q = (i & 127) >> 1, h = i & 1;
    float* f = (float*)&g_tabU[chunk_base(c) + q];
    f[h]     = ax;   // low/high half of .x
    f[2 + h] = l2;   // low/high half of .y
}

// 2 threads per row: thread half h owns chunks [8h, 8h+8).
__global__ __launch_bounds__(TPB) void sample_kernel(
    const float* __restrict__ mean,
    const float* __restrict__ stdv,
    const float* __restrict__ uni,
    float* __restrict__ out)
{
    __shared__ ulonglong2 tab[TABSZ];   // 16656 B

    const int tid  = threadIdx.x;
    for (int i = tid; i < TABSZ; i += TPB) tab[i] = g_tabU[i];
    __syncthreads();

    const int gt   = blockIdx.x * TPB + tid;
    const int row  = gt >> 1;
    const int half = gt & 1;
    const int lane = tid & 31;

    const float mu = __ldg(mean + row);
    const float sg = __ldg(stdv + row) + EPSF;
    const float u  = __ldg(uni + row);
    const float k2 = (-0.5f * LOG2E) / (sg * sg);

    const u64 nmu   = pk(-mu, -mu);
    const u64 k2p   = pk(k2, k2);
    const u64 magicP = pk(MAGICF, MAGICF);
    const u64 c5p = pk(1.3333558e-3f, 1.3333558e-3f);
    const u64 c4p = pk(9.6181291e-3f, 9.6181291e-3f);
    const u64 c3p = pk(5.5504109e-2f, 5.5504109e-2f);
    const u64 c2p = pk(2.4022651e-1f, 2.4022651e-1f);
    const u64 c1p = pk(6.9314718e-1f, 6.9314718e-1f);
    const u64 c0p = pk(1.0f, 1.0f);

    // ---- Phase 1: 2 sub-sums per chunk (16 regs); hybrid MUFU/poly exp ----
    float ss[CPT * 2];
    float ps = 0.0f;
    #pragma unroll
    for (int c = 0; c < CPT; ++c) {
        const ulonglong2* cp = tab + chunk_base(half * CPT + c);
        float csum = 0.0f;
        #pragma unroll
        for (int sb = 0; sb < 2; ++sb) {
            float s0 = 0.0f, s1 = 0.0f;
            u64 sp = pk(0.0f, 0.0f);
            #pragma unroll 16
            for (int jj = 0; jj < 32; ++jj) {
                int j = sb * 32 + jj;
                ulonglong2 v = cp[j];   // LDS.128 -> two u64 pairs, no packing
                u64 t, tt, arg;
                ADD2(t, v.x, nmu);
                MUL2(tt, t, t);
                FMA2(arg, tt, k2p, v.y);
                if ((j & 15) < 3) {
                    // packed poly exp2 on fma pipe (beta = 3/16); clamp on alu
                    float alo, ahi;
                    upk(alo, ahi, arg);
                    alo = fmaxf(alo, -120.0f);
                    ahi = fmaxf(ahi, -120.0f);
                    arg = pk(alo, ahi);
                    u64 m, iv, f, p;
                    ADD2(m, arg, magicP);
                    SUB2(iv, m, magicP);
                    SUB2(f, arg, iv);
                    FMA2(p, c5p, f, c4p);
                    FMA2(p, p,  f, c3p);
                    FMA2(p, p,  f, c2p);
                    FMA2(p, p,  f, c1p);
                    FMA2(p, p,  f, c0p);
                    u32 mlo = (u32)m, mhi = (u32)(m >> 32);
                    u32 plo = (u32)p, phi = (u32)(p >> 32);
                    float rlo = __uint_as_float(plo + (mlo << 23));
                    float rhi = __uint_as_float(phi + (mhi << 23));
                    u64 r = pk(rlo, rhi);
                    ADD2(sp, sp, r);
                } else {
                    float lo, hi;
                    upk(lo, hi, arg);
                    s0 += ex2(lo);
                    s1 += ex2(hi);
                }
            }
            float splo, sphi;
            upk(splo, sphi, sp);
            float v = (s0 + s1) + (splo + sphi);
            ss[c * 2 + sb] = v;
            csum = sb ? (csum + v) : v;
        }
        ps += csum;   // ps accumulation order == phase-2a walk order
    }

    // ---- Pair handoff: excl (exact boundary) and shared S ----
    float pso = __shfl_xor_sync(FULLMASK, ps, 1);     // partner's ps
    float excl = half ? pso : 0.0f;
    float cum = excl;
    #pragma unroll
    for (int c = 0; c < CPT; ++c) cum += (ss[2 * c] + ss[2 * c + 1]);
    float S = __shfl_sync(FULLMASK, cum, lane | 1);   // exact sequential full sum

    const float invnorm = rsqrtf(6.283185307179586f * sg * sg);
    const float denom   = __fmaf_rn(invnorm, S, EPSF);
    const float Traw    = u * denom / invnorm;

    // ---- Phase 2a: crossing chunk + sub-block within my half ----
    int kc = -1, sub = 0;
    float base = 0.0f;
    float c2w = excl;
    #pragma unroll
    for (int c = 0; c < CPT; ++c) {
        float ni = c2w + (ss[2 * c] + ss[2 * c + 1]);
        if (kc < 0 && ni > Traw) { kc = half * CPT + c; base = c2w; }
        c2w = ni;
    }
    if (excl > Traw) kc = -1;   // partner already crossed

    unsigned bal = __ballot_sync(FULLMASK, kc >= 0);
    bool pair_none = (((bal >> (lane & ~1)) & 3u) == 0u);
    bool am_writer = (kc >= 0) || (pair_none && half == 1);

    if (am_writer) {
        int idx;
        if (kc < 0) {
            float Snorm = invnorm * S;
            float cl = Snorm / (Snorm + EPSF);   // reference's cdf[last]
            idx = (u < cl) ? (NSAMP - 1) : 0;
        } else {
            // pick sub-block: a = [0,32) pairs, b = [32,64)
            int lc = kc - half * CPT;
            float ssa = ss[2 * lc];
            if (base + ssa > Traw) { sub = 0; }
            else                   { sub = 1; base = base + ssa; }

            // ---- Phase 2b: rewalk 32 pairs of the sub-block (exact ex2) ----
            const float T2 = Traw - base;
            const ulonglong2* cp = tab + chunk_base(kc) + sub * 32;
            float c = 0.0f;
            idx = -1;
            #pragma unroll 8
            for (int j = 0; j < 32; ++j) {
                const float4 v = *(const float4*)(cp + j);  // (ax0,ax1,l20,l21)
                float t0 = v.x - mu;
                float p0 = ex2(__fmaf_rn(t0 * t0, k2, v.z));
                c += p0;
                if (idx < 0 && c > T2) idx = kc * CPTS + sub * 64 + 2 * j;
                float t1 = v.y - mu;
                float p1 = ex2(__fmaf_rn(t1 * t1, k2, v.w));
                c += p1;
                if (idx < 0 && c > T2) idx = kc * CPTS + sub * 64 + 2 * j + 1;
            }
            if (idx < 0) idx = kc * CPTS + sub * 64 + 63;  // fp drift at boundary
            if (idx > NSAMP - 1) idx = NSAMP - 1;
        }

        // ---- Recompute prob at final index (exact ex2) ----
        int cc = idx >> 7, q = (idx & 127) >> 1, h = idx & 1;
        const float4 v = *(const float4*)(tab + chunk_base(cc) + q);
        float ax = h ? v.y : v.x;
        float l2 = h ? v.w : v.z;
        float t = ax - mu;
        float p = ex2(__fmaf_rn(t * t, k2, l2));
        float prob = invnorm * p / denom;

        out[row]         = __ldg(g_grid + idx);
        out[NROWS + row] = prob;
    }
}

extern "C" void kernel_launch(void* const* d_in, const int* in_sizes, int n_in,
                              void* d_out, int out_size) {
    const float* mean = (const float*)d_in[0];
    const float* stdv = (const float*)d_in[1];
    const float* uni  = (const float*)d_in[2];
    float* out = (float*)d_out;

    init_tables_kernel<<<2, 1024>>>();
    sample_kernel<<<NBLK, TPB>>>(mean, stdv, uni, out);
}

// round 10
// speedup vs baseline: 1.2971x; 1.2319x over previous
#include <cuda_runtime.h>

#define EPSF     1.1920928955078125e-07f
#define LOG2E    1.4426950408889634f
#define NSAMP    2000
#define NPAD     2048
#define Y0F      0.9999f
#define NROWS    65536
#define FULLMASK 0xffffffffu

#define NCH      16      // chunks per row
#define CPT      8       // chunks per thread (2 threads/row)
#define CPTS     128     // points per chunk
#define CF4P     65      // padded chunk stride (16B units)
#define TABSZ    (NCH * CF4P + 1)

// Table entry: .x = (ax_{2i}, ax_{2i+1}) packed, .y = (l2_{2i}, l2_{2i+1}) packed.
__device__ ulonglong2 g_tabU[TABSZ];
__device__ float      g_grid[NPAD];

typedef unsigned long long u64;

__device__ __forceinline__ float ex2(float x) {
    float r;
    asm("ex2.approx.ftz.f32 %0, %1;" : "=f"(r) : "f"(x));
    return r;
}
__device__ __forceinline__ u64 pk(float a, float b) {
    u64 r;
    asm("mov.b64 %0, {%1, %2};" : "=l"(r) : "f"(a), "f"(b));
    return r;
}
__device__ __forceinline__ void upk(float& a, float& b, u64 r) {
    asm("mov.b64 {%0, %1}, %2;" : "=f"(a), "=f"(b) : "l"(r));
}
#define ADD2(d,a,b) asm("add.rn.f32x2 %0, %1, %2;"     : "=l"(d) : "l"(a), "l"(b))
#define MUL2(d,a,b) asm("mul.rn.f32x2 %0, %1, %2;"     : "=l"(d) : "l"(a), "l"(b))
#define FMA2(d,a,b,c) asm("fma.rn.f32x2 %0, %1, %2, %3;" : "=l"(d) : "l"(a), "l"(b), "l"(c))

#define TPB      128
#define NBLK     (NROWS * 2 / TPB)   // 1024

__device__ __forceinline__ int chunk_base(int c) { return c * CF4P + (c >> 3); }

__global__ void init_tables_kernel() {
    int i = blockIdx.x * blockDim.x + threadIdx.x;  // 0..2047
    if (i >= NPAD) return;
    const float step = 2.0f * Y0F / 1999.0f;
    float ax, l2, g;
    if (i < NSAMP) {
        float x = (i == NSAMP - 1) ? Y0F
                                   : __fadd_rn(__fmul_rn((float)i, step), -Y0F);
        ax = 0.5f * logf((1.0f + x) / (1.0f - x) + EPSF);
        l2 = -log2f(1.0f - x * x);
        g  = x;
    } else {
        ax = 0.0f; l2 = -1e30f; g = Y0F;   // padding inert
    }
    g_grid[i] = g;
    int c = i >> 7, q = (i & 127) >> 1, h = i & 1;
    float* f = (float*)&g_tabU[chunk_base(c) + q];
    f[h]     = ax;   // low/high half of .x
    f[2 + h] = l2;   // low/high half of .y
}

// 2 threads per row: thread half h owns chunks [8h, 8h+8).
__global__ __launch_bounds__(TPB) void sample_kernel(
    const float* __restrict__ mean,
    const float* __restrict__ stdv,
    const float* __restrict__ uni,
    float* __restrict__ out)
{
    __shared__ ulonglong2 tab[TABSZ];   // 16656 B

    const int tid  = threadIdx.x;
    for (int i = tid; i < TABSZ; i += TPB) tab[i] = g_tabU[i];
    __syncthreads();

    const int gt   = blockIdx.x * TPB + tid;
    const int row  = gt >> 1;
    const int half = gt & 1;
    const int lane = tid & 31;

    const float mu = __ldg(mean + row);
    const float sg = __ldg(stdv + row) + EPSF;
    const float u  = __ldg(uni + row);
    const float k2 = (-0.5f * LOG2E) / (sg * sg);

    const u64 nmu = pk(-mu, -mu);
    const u64 k2p = pk(k2, k2);

    // ---- Phase 1: 2 sub-sums per chunk; pure-MUFU exp, minimal instrs ----
    float ss[CPT * 2];
    float ps = 0.0f;
    #pragma unroll
    for (int c = 0; c < CPT; ++c) {
        const ulonglong2* cp = tab + chunk_base(half * CPT + c);
        float csum = 0.0f;
        #pragma unroll
        for (int sb = 0; sb < 2; ++sb) {
            float s0 = 0.0f, s1 = 0.0f;
            #pragma unroll 16
            for (int jj = 0; jj < 32; ++jj) {
                ulonglong2 v = cp[sb * 32 + jj];  // LDS.128 -> two u64 pairs
                u64 t, tt, arg;
                ADD2(t, v.x, nmu);
                MUL2(tt, t, t);
                FMA2(arg, tt, k2p, v.y);
                float lo, hi;
                upk(lo, hi, arg);
                s0 += ex2(lo);
                s1 += ex2(hi);
            }
            float v = s0 + s1;
            ss[c * 2 + sb] = v;
            csum = sb ? (csum + v) : v;
        }
        ps += csum;   // same accumulation order as phase-2a walk
    }

    // ---- Pair handoff: excl (exact boundary) and shared S ----
    float pso = __shfl_xor_sync(FULLMASK, ps, 1);     // partner's ps
    float excl = half ? pso : 0.0f;
    float cum = excl;
    #pragma unroll
    for (int c = 0; c < CPT; ++c) cum += (ss[2 * c] + ss[2 * c + 1]);
    float S = __shfl_sync(FULLMASK, cum, lane | 1);   // exact sequential full sum

    const float invnorm = rsqrtf(6.283185307179586f * sg * sg);
    const float denom   = __fmaf_rn(invnorm, S, EPSF);
    const float Traw    = u * denom / invnorm;

    // ---- Phase 2a: crossing chunk + sub-block within my half ----
    int kc = -1, sub = 0;
    float base = 0.0f;
    float c2w = excl;
    #pragma unroll
    for (int c = 0; c < CPT; ++c) {
        float ni = c2w + (ss[2 * c] + ss[2 * c + 1]);
        if (kc < 0 && ni > Traw) { kc = half * CPT + c; base = c2w; }
        c2w = ni;
    }
    if (excl > Traw) kc = -1;   // partner already crossed

    unsigned bal = __ballot_sync(FULLMASK, kc >= 0);
    bool pair_none = (((bal >> (lane & ~1)) & 3u) == 0u);
    bool am_writer = (kc >= 0) || (pair_none && half == 1);

    if (am_writer) {
        int idx;
        if (kc < 0) {
            float Snorm = invnorm * S;
            float cl = Snorm / (Snorm + EPSF);   // reference's cdf[last]
            idx = (u < cl) ? (NSAMP - 1) : 0;
        } else {
            // pick sub-block: a = [0,32) pairs, b = [32,64)
            int lc = kc - half * CPT;
            float ssa = ss[2 * lc];
            if (base + ssa > Traw) { sub = 0; }
            else                   { sub = 1; base = base + ssa; }

            // ---- Phase 2b: rewalk 32 pairs of the sub-block (exact ex2) ----
            const float T2 = Traw - base;
            const ulonglong2* cp = tab + chunk_base(kc) + sub * 32;
            float c = 0.0f;
            idx = -1;
            #pragma unroll 8
            for (int j = 0; j < 32; ++j) {
                const float4 v = *(const float4*)(cp + j);  // (ax0,ax1,l20,l21)
                float t0 = v.x - mu;
                float p0 = ex2(__fmaf_rn(t0 * t0, k2, v.z));
                c += p0;
                if (idx < 0 && c > T2) idx = kc * CPTS + sub * 64 + 2 * j;
                float t1 = v.y - mu;
                float p1 = ex2(__fmaf_rn(t1 * t1, k2, v.w));
                c += p1;
                if (idx < 0 && c > T2) idx = kc * CPTS + sub * 64 + 2 * j + 1;
            }
            if (idx < 0) idx = kc * CPTS + sub * 64 + 63;  // fp drift at boundary
            if (idx > NSAMP - 1) idx = NSAMP - 1;
        }

        // ---- Recompute prob at final index (exact ex2) ----
        int cc = idx >> 7, q = (idx & 127) >> 1, h = idx & 1;
        const float4 v = *(const float4*)(tab + chunk_base(cc) + q);
        float ax = h ? v.y : v.x;
        float l2 = h ? v.w : v.z;
        float t = ax - mu;
        float p = ex2(__fmaf_rn(t * t, k2, l2));
        float prob = invnorm * p / denom;

        out[row]         = __ldg(g_grid + idx);
        out[NROWS + row] = prob;
    }
}

extern "C" void kernel_launch(void* const* d_in, const int* in_sizes, int n_in,
                              void* d_out, int out_size) {
    const float* mean = (const float*)d_in[0];
    const float* stdv = (const float*)d_in[1];
    const float* uni  = (const float*)d_in[2];
    float* out = (float*)d_out;

    init_tables_kernel<<<2, 1024>>>();
    sample_kernel<<<NBLK, TPB>>>(mean, stdv, uni, out);
}